// round 14
// baseline (speedup 1.0000x reference)
#include <cuda_runtime.h>

// PBKDF2-toy, serial single-warp register kernel. R14: seam-cost experiment.
// Settled model: cycles/iter = issue slots (~311) + stalls (~50), of which
// loop-back seams cost ~17 cyc each (measured R10: unroll2 vs unroll4 =
// +2.26us for +250 seams). R8 structure (best, 184.4us) with unroll 4 -> 8:
// 125 seams, ~1.1us predicted saving; risk is the ~39KB body vs 32KB L1.5
// I$ (sequential stream, prefetch-overlapped per B300 doc). All other
// levers (pipe balance, SWAR, spill, placement) measured dead R5-R13.
// Harness dtype shims: float32 out, dtype-sniffed in (proven R3).

__device__ __forceinline__ unsigned load_byte(const void* p, int i) {
    int v = ((const int*)p)[i];
    if ((unsigned)v <= 255u) return (unsigned)v;   // int32 input
    return (unsigned)(int)__int_as_float(v);       // float32 input
}

// hi*65536 + lo as a single IMAD (fma pipe); benign to scheduling (R8).
__device__ __forceinline__ unsigned pack16(unsigned hi, unsigned lo) {
    unsigned t;
    asm("mad.lo.u32 %0, %1, 65536, %2;" : "=r"(t) : "r"(hi), "r"(lo));
    return t;
}

__global__ void __launch_bounds__(32, 1)
Model_62955630625117_kernel(const void* __restrict__ pw_in,
                            const void* __restrict__ salt_in,
                            float* __restrict__ out) {
    // All lanes uniform & convergent; lane 0 writes at the end.
    unsigned c[16];    // (pw[j]*31) & 255, loop-invariant
    unsigned r[32];    // hash state U (mix LOP3 keeps bytes 8-bit)
    unsigned Fp[16];   // packed xor accumulator: lo16 = F[i], hi16 = F[i+16]

    #pragma unroll
    for (int j = 0; j < 16; j++) {
        unsigned p = load_byte(pw_in, j);
        c[j] = (p * 31u) & 255u;
        r[j] = p;
    }
    #pragma unroll
    for (int j = 0; j < 16; j++) r[16 + j] = load_byte(salt_in, j);

    // First hmac message = salt(16) ++ block_num{0,0,0,1}
    r[0] = c[0];
    r[1] = c[1];
    r[2] = c[2];
    r[3] = (c[3] + 1u) & 255u;

    // U0 mix
    #pragma unroll
    for (int rd = 0; rd < 4; rd++) {
        #pragma unroll
        for (int i = 0; i < 32; i++)
            r[i] = (r[i] ^ (r[(i + 17) & 31] + r[(i + 11) & 31])) & 255u;
    }
    #pragma unroll
    for (int i = 0; i < 16; i++)
        Fp[i] = pack16(r[i + 16], r[i]);           // F init = U0 (packed)

    // 999 chained iterations: U = hmac(pw, U); Fp ^= packed(U).
    // Absorb collapse: r[j] = c[j] + r[16+j] (9-bit OK, mix LOP3 re-masks),
    // r[16+j] = old r[j] (order-2 swap; even unroll -> pure renaming).
    // 999 = 8*124 + 7: peel 7 iterations so the main loop unrolls x8 clean.
    #pragma unroll 1
    for (int blk = 0; blk < 125; blk++) {
        int inner = (blk == 0) ? 7 : 8;
        #pragma unroll 8
        for (int s = 0; s < inner; s++) {
            #pragma unroll
            for (int j = 0; j < 16; j++) {
                unsigned t = r[j];
                r[j] = c[j] + r[16 + j];
                r[16 + j] = t;
            }
            #pragma unroll
            for (int rd = 0; rd < 3; rd++) {
                #pragma unroll
                for (int i = 0; i < 32; i++)
                    r[i] = (r[i] ^ (r[(i + 17) & 31] + r[(i + 11) & 31])) & 255u;
            }
            // round 4: steps 0..15 plain; 16..31 fused with packed F-xor
            #pragma unroll
            for (int i = 0; i < 16; i++)
                r[i] = (r[i] ^ (r[(i + 17) & 31] + r[(i + 11) & 31])) & 255u;
            #pragma unroll
            for (int i = 16; i < 32; i++) {
                r[i] = (r[i] ^ (r[(i + 17) & 31] + r[(i + 11) & 31])) & 255u;
                Fp[i - 16] ^= pack16(r[i], r[i - 16]);  // IMAD + LOP3
            }
        }
    }

    if (threadIdx.x == 0) {
        #pragma unroll
        for (int i = 0; i < 16; i++) {
            out[i]      = (float)(Fp[i] & 0xFFFFu);
            out[i + 16] = (float)(Fp[i] >> 16);
        }
    }
}

extern "C" void kernel_launch(void* const* d_in, const int* in_sizes, int n_in,
                              void* d_out, int out_size) {
    const void* password = d_in[0];
    const void* salt     = (n_in >= 2) ? d_in[1] : (const void*)((const int*)d_in[0] + 16);
    float* out           = (float*)d_out;
    Model_62955630625117_kernel<<<1, 32>>>(password, salt, out);
}

// round 15
// speedup vs baseline: 1.1941x; 1.1941x over previous
#include <cuda_runtime.h>

// PBKDF2-toy, serial single-warp register kernel. R15: clean unroll-8.
// R14 blew up (455us) because the variable inner trip count killed
// unrolling entirely -- lesson: constant bounds only. This is the best
// kernel (R8, 184.4us) with exactly one change: #pragma unroll 4 -> 8 on
// the plain constant-bound loop (ptxas peels 999%8 itself, proven benign
// at unroll 4). Seam model (R10: ~17cyc/seam) predicts ~1.1us saving at
// 125 seams; I$ pressure (~39KB body vs 32KB L1.5) is the counter-risk.
// Settled model: cycles/iter = issue slots (~311) + ~50 stalls; pipe
// split, SWAR, smem spill, placement all measured dead (R5-R13).
// Harness dtype shims: float32 out, dtype-sniffed in (proven R3).

__device__ __forceinline__ unsigned load_byte(const void* p, int i) {
    int v = ((const int*)p)[i];
    if ((unsigned)v <= 255u) return (unsigned)v;   // int32 input
    return (unsigned)(int)__int_as_float(v);       // float32 input
}

// hi*65536 + lo as a single IMAD (fma pipe); benign to scheduling (R8).
__device__ __forceinline__ unsigned pack16(unsigned hi, unsigned lo) {
    unsigned t;
    asm("mad.lo.u32 %0, %1, 65536, %2;" : "=r"(t) : "r"(hi), "r"(lo));
    return t;
}

__global__ void __launch_bounds__(32, 1)
Model_62955630625117_kernel(const void* __restrict__ pw_in,
                            const void* __restrict__ salt_in,
                            float* __restrict__ out) {
    // All lanes uniform & convergent; lane 0 writes at the end.
    unsigned c[16];    // (pw[j]*31) & 255, loop-invariant
    unsigned r[32];    // hash state U (mix LOP3 keeps bytes 8-bit)
    unsigned Fp[16];   // packed xor accumulator: lo16 = F[i], hi16 = F[i+16]

    #pragma unroll
    for (int j = 0; j < 16; j++) {
        unsigned p = load_byte(pw_in, j);
        c[j] = (p * 31u) & 255u;
        r[j] = p;
    }
    #pragma unroll
    for (int j = 0; j < 16; j++) r[16 + j] = load_byte(salt_in, j);

    // First hmac message = salt(16) ++ block_num{0,0,0,1}
    r[0] = c[0];
    r[1] = c[1];
    r[2] = c[2];
    r[3] = (c[3] + 1u) & 255u;

    // U0 mix
    #pragma unroll
    for (int rd = 0; rd < 4; rd++) {
        #pragma unroll
        for (int i = 0; i < 32; i++)
            r[i] = (r[i] ^ (r[(i + 17) & 31] + r[(i + 11) & 31])) & 255u;
    }
    #pragma unroll
    for (int i = 0; i < 16; i++)
        Fp[i] = pack16(r[i + 16], r[i]);           // F init = U0 (packed)

    // 999 chained iterations: U = hmac(pw, U); Fp ^= packed(U).
    // Absorb collapse: r[j] = c[j] + r[16+j] (9-bit OK, mix LOP3 re-masks),
    // r[16+j] = old r[j] (order-2 swap; even unroll -> pure renaming).
    #pragma unroll 8
    for (int it = 1; it < 1000; it++) {
        #pragma unroll
        for (int j = 0; j < 16; j++) {
            unsigned t = r[j];
            r[j] = c[j] + r[16 + j];
            r[16 + j] = t;
        }
        #pragma unroll
        for (int rd = 0; rd < 3; rd++) {
            #pragma unroll
            for (int i = 0; i < 32; i++)
                r[i] = (r[i] ^ (r[(i + 17) & 31] + r[(i + 11) & 31])) & 255u;
        }
        // round 4: steps 0..15 plain; steps 16..31 fused with packed F-xor
        #pragma unroll
        for (int i = 0; i < 16; i++)
            r[i] = (r[i] ^ (r[(i + 17) & 31] + r[(i + 11) & 31])) & 255u;
        #pragma unroll
        for (int i = 16; i < 32; i++) {
            r[i] = (r[i] ^ (r[(i + 17) & 31] + r[(i + 11) & 31])) & 255u;
            Fp[i - 16] ^= pack16(r[i], r[i - 16]);  // IMAD (fma) + LOP3 (alu)
        }
    }

    if (threadIdx.x == 0) {
        #pragma unroll
        for (int i = 0; i < 16; i++) {
            out[i]      = (float)(Fp[i] & 0xFFFFu);
            out[i + 16] = (float)(Fp[i] >> 16);
        }
    }
}

extern "C" void kernel_launch(void* const* d_in, const int* in_sizes, int n_in,
                              void* d_out, int out_size) {
    const void* password = d_in[0];
    const void* salt     = (n_in >= 2) ? d_in[1] : (const void*)((const int*)d_in[0] + 16);
    float* out           = (float*)d_out;
    Model_62955630625117_kernel<<<1, 32>>>(password, salt, out);
}

// round 16
// speedup vs baseline: 2.4587x; 2.0592x over previous
#include <cuda_runtime.h>

// PBKDF2-toy, serial single-warp register kernel — certified final (R8
// config, measured 184.4us, issue 85.7%, regs 96). 15-round evidence:
// - Floor = ~311 issue slots/iter on one warp (~164us); best = floor + ~50
//   stall cyc/iter. Residual stalls are register-bank/scoreboard effects
//   not reachable from CUDA source.
// - Wins kept: absorb collapsed to 16 adds + renamed swap (mod-256 deferred
//   to the mix LOP3's fused mask), hoisted key contribution c[]=pw*31,
//   packed F-fold (16 pack16-IMAD + 16 LOP3 fused into mix round 4 at
//   operand-ready points), unroll 4 (bracketed: 2=186.7, 4=184.4, 8=381).
// - Levers measured dead: pipe rebalance (R9/R11), SWAR (R12), smem spill
//   (R6), op placement (R13), uniform-path (R5), variable trip counts (R14).
// Harness dtype shims: float32 out, dtype-sniffed in (proven R3).

__device__ __forceinline__ unsigned load_byte(const void* p, int i) {
    int v = ((const int*)p)[i];
    if ((unsigned)v <= 255u) return (unsigned)v;   // int32 input
    return (unsigned)(int)__int_as_float(v);       // float32 input
}

// hi*65536 + lo as a single IMAD (fma pipe); benign to scheduling (R8).
__device__ __forceinline__ unsigned pack16(unsigned hi, unsigned lo) {
    unsigned t;
    asm("mad.lo.u32 %0, %1, 65536, %2;" : "=r"(t) : "r"(hi), "r"(lo));
    return t;
}

__global__ void __launch_bounds__(32, 1)
Model_62955630625117_kernel(const void* __restrict__ pw_in,
                            const void* __restrict__ salt_in,
                            float* __restrict__ out) {
    // All lanes uniform & convergent; lane 0 writes at the end.
    unsigned c[16];    // (pw[j]*31) & 255, loop-invariant
    unsigned r[32];    // hash state U (mix LOP3 keeps bytes 8-bit)
    unsigned Fp[16];   // packed xor accumulator: lo16 = F[i], hi16 = F[i+16]

    #pragma unroll
    for (int j = 0; j < 16; j++) {
        unsigned p = load_byte(pw_in, j);
        c[j] = (p * 31u) & 255u;
        r[j] = p;
    }
    #pragma unroll
    for (int j = 0; j < 16; j++) r[16 + j] = load_byte(salt_in, j);

    // First hmac message = salt(16) ++ block_num{0,0,0,1}
    r[0] = c[0];
    r[1] = c[1];
    r[2] = c[2];
    r[3] = (c[3] + 1u) & 255u;

    // U0 mix
    #pragma unroll
    for (int rd = 0; rd < 4; rd++) {
        #pragma unroll
        for (int i = 0; i < 32; i++)
            r[i] = (r[i] ^ (r[(i + 17) & 31] + r[(i + 11) & 31])) & 255u;
    }
    #pragma unroll
    for (int i = 0; i < 16; i++)
        Fp[i] = pack16(r[i + 16], r[i]);           // F init = U0 (packed)

    // 999 chained iterations: U = hmac(pw, U); Fp ^= packed(U).
    // Absorb collapse: r[j] = c[j] + r[16+j] (9-bit OK, mix LOP3 re-masks),
    // r[16+j] = old r[j] (order-2 swap; even unroll -> pure renaming).
    #pragma unroll 4
    for (int it = 1; it < 1000; it++) {
        #pragma unroll
        for (int j = 0; j < 16; j++) {
            unsigned t = r[j];
            r[j] = c[j] + r[16 + j];
            r[16 + j] = t;
        }
        #pragma unroll
        for (int rd = 0; rd < 3; rd++) {
            #pragma unroll
            for (int i = 0; i < 32; i++)
                r[i] = (r[i] ^ (r[(i + 17) & 31] + r[(i + 11) & 31])) & 255u;
        }
        // round 4: steps 0..15 plain; steps 16..31 fused with packed F-xor
        #pragma unroll
        for (int i = 0; i < 16; i++)
            r[i] = (r[i] ^ (r[(i + 17) & 31] + r[(i + 11) & 31])) & 255u;
        #pragma unroll
        for (int i = 16; i < 32; i++) {
            r[i] = (r[i] ^ (r[(i + 17) & 31] + r[(i + 11) & 31])) & 255u;
            Fp[i - 16] ^= pack16(r[i], r[i - 16]);  // IMAD (fma) + LOP3 (alu)
        }
    }

    if (threadIdx.x == 0) {
        #pragma unroll
        for (int i = 0; i < 16; i++) {
            out[i]      = (float)(Fp[i] & 0xFFFFu);
            out[i + 16] = (float)(Fp[i] >> 16);
        }
    }
}

extern "C" void kernel_launch(void* const* d_in, const int* in_sizes, int n_in,
                              void* d_out, int out_size) {
    const void* password = d_in[0];
    const void* salt     = (n_in >= 2) ? d_in[1] : (const void*)((const int*)d_in[0] + 16);
    float* out           = (float*)d_out;
    Model_62955630625117_kernel<<<1, 32>>>(password, salt, out);
}